// round 10
// baseline (speedup 1.0000x reference)
#include <cuda_runtime.h>
#include <cstdint>
#include <cstddef>

#define Bsz  64
#define Hd   512
#define Tlen 512
#define G4H  2048
#define Ed   256
#define NCTA 128
#define NTHR 512
#define HB   (Hd * Bsz)

typedef unsigned long long ull;

// ---------------- device scratch (static, allowed) ----------------
__device__ __align__(256) float g_xg[(size_t)Tlen * G4H * Bsz];  // 256 MB
__device__ __align__(256) float g_h0[2 * HB];
__device__ __align__(256) float g_h1[2 * HB];
__device__ unsigned g_bar1;
__device__ unsigned g_bar2;

// ---------------- helpers ----------------
typedef unsigned u32;
__device__ __forceinline__ ull pk2f(float x) {
    ull r; asm("mov.b64 %0, {%1, %1};" : "=l"(r) : "f"(x)); return r;
}
__device__ __forceinline__ void ffma2(ull& a, ull h, ull w) {
    asm("fma.rn.f32x2 %0, %1, %2, %0;" : "+l"(a) : "l"(h), "l"(w));
}
__device__ __forceinline__ void up2(ull v, float& x, float& y) {
    u32 lo, hi;
    asm("mov.b64 {%0, %1}, %2;" : "=r"(lo), "=r"(hi) : "l"(v));
    x = __uint_as_float(lo); y = __uint_as_float(hi);
}
__device__ __forceinline__ float sigm(float x) {
    return __fdividef(1.f, 1.f + __expf(-x));
}
__device__ __forceinline__ float tanh_fast(float x) {
    float e = __expf(2.f * x);
    return 1.f - __fdividef(2.f, e + 1.f);
}
__device__ __forceinline__ u32 totf32(float x) {
    u32 r; asm("cvt.rna.tf32.f32 %0, %1;" : "=r"(r) : "f"(x)); return r;
}
__device__ __forceinline__ void mma8(float (&d)[4], u32 a0, u32 a1, u32 a2, u32 a3,
                                     u32 b0, u32 b1) {
    asm("mma.sync.aligned.m16n8k8.row.col.f32.tf32.tf32.f32 "
        "{%0,%1,%2,%3}, {%4,%5,%6,%7}, {%8,%9}, {%0,%1,%2,%3};"
        : "+f"(d[0]), "+f"(d[1]), "+f"(d[2]), "+f"(d[3])
        : "r"(a0), "r"(a1), "r"(a2), "r"(a3), "r"(b0), "r"(b1));
}

// ---------------- split grid barrier (monotonic) ----------------
__device__ __forceinline__ void bar_arrive(unsigned* ctr) {
    if (threadIdx.x == 0)
        asm volatile("red.release.gpu.global.add.u32 [%0], 1;" :: "l"(ctr) : "memory");
}
__device__ __forceinline__ void bar_wait(unsigned* ctr, unsigned target) {
    if (threadIdx.x == 0) {
        unsigned v;
        do {
            asm volatile("ld.acquire.gpu.global.u32 %0, [%1];" : "=r"(v) : "l"(ctr) : "memory");
        } while (v < target);
    }
    __syncthreads();
}

// =================================================================
// Kernel A (unchanged fp32 f32x2 version from R8)
// =================================================================
__global__ void __launch_bounds__(256) kA(const int* __restrict__ x,
                                          const float* __restrict__ emb,
                                          const float* __restrict__ Wih0,
                                          const float* __restrict__ b0) {
    __shared__ float ws[64 * 33];
    __shared__ float xs2[32 * 66];
    __shared__ int   xr[64];
    const int tid = threadIdx.x;
    const int t   = blockIdx.x;
    const int rb  = blockIdx.y * 64;
    if (tid < 64) xr[tid] = x[tid * Tlen + t];
    __syncthreads();

    ull accA[4], accB[4];
#pragma unroll
    for (int j = 0; j < 4; j++) { accA[j] = 0ull; accB[j] = 0ull; }
    const int r4 = tid >> 4;
    const int q4 = (tid & 15) * 4;

    for (int ec = 0; ec < Ed; ec += 32) {
#pragma unroll
        for (int i = 0; i < 8; i++) {
            int idx = tid + i * 256;
            int a = idx >> 5, e = idx & 31;
            ws[a * 33 + e] = Wih0[(rb + a) * Ed + ec + e];
            xs2[e * 66 + a] = emb[(size_t)xr[a] * Ed + ec + e];
        }
        __syncthreads();
#pragma unroll 8
        for (int e = 0; e < 32; e++) {
            ull x01 = *(const ull*)&xs2[e * 66 + q4];
            ull x23 = *(const ull*)&xs2[e * 66 + q4 + 2];
#pragma unroll
            for (int j = 0; j < 4; j++) {
                ull w2 = pk2f(ws[(r4 * 4 + j) * 33 + e]);
                ffma2(accA[j], x01, w2);
                ffma2(accB[j], x23, w2);
            }
        }
        __syncthreads();
    }
#pragma unroll
    for (int j = 0; j < 4; j++) {
        int row = rb + r4 * 4 + j;
        float bv = b0[row];
        float4 o;
        up2(accA[j], o.x, o.y);
        up2(accB[j], o.z, o.w);
        o.x += bv; o.y += bv; o.z += bv; o.w += bv;
        *(float4*)(g_xg + ((size_t)t * G4H + row) * Bsz + q4) = o;
    }
}

// =================================================================
__global__ void kzero() {
    int i = blockIdx.x * 256 + threadIdx.x;   // grid 256 -> 65536 = 2*HB
    g_h0[i] = 0.f;
    g_h1[i] = 0.f;
    if (i == 0) { g_bar1 = 0u; g_bar2 = 0u; }
}

// =================================================================
// Persistent recurrent kernel with mma.sync tf32 (3-pass hi/lo).
// 128 CTAs x 512 threads (16 warps = 8 n-tiles x 2 k-halves).
// CTA owns 4 units = 16 gate rows (row j: j&3 = gate, j>>2 = unit).
// A-fragments (weights) pre-packed per-lane in smem; B (h) loaded
// fp32 from L2 and split to tf32 hi/lo in registers.
// smem floats: AW0H/L [64*128]x2 | AW1IH/L x2 | AW1HH/L x2 | pbuf[2][16][66]
// =================================================================
#define AW0H   0
#define AW0L   8192
#define AW1IH  16384
#define AW1IL  24576
#define AW1HH  32768
#define AW1HL  40960
#define PBUF   49152
#define SMTOT  (49152 + 2 * 16 * 66)
#define SMEMB  (SMTOT * 4)

// stage one 16x512 weight tile as packed per-lane tf32 A-fragments
__device__ void stage_w(const float* __restrict__ W, float* hi, float* lo, int u0) {
    for (int idx = threadIdx.x; idx < 64 * 128; idx += NTHR) {
        int kstep = idx >> 7, lane = (idx >> 2) & 31, reg = idx & 3;
        int gid = lane >> 2, tig = lane & 3;
        int j = gid + ((reg & 1) << 3);           // A row 0..15
        int k = kstep * 8 + tig + ((reg >> 1) << 2);
        int grow = ((j & 3) << 9) + u0 + (j >> 2);
        float w = W[grow * Hd + k];
        u32 h = totf32(w);
        float hf = __uint_as_float(h);
        hi[idx] = hf;
        lo[idx] = __uint_as_float(totf32(w - hf));
    }
}

// 32 k-steps of m16n8k8 tf32, 3 passes; A from packed smem, B from global fp32.
__device__ __forceinline__ void mma_slice(float (&d)[4], const float4* __restrict__ ah,
                                          const float4* __restrict__ al,
                                          const float* __restrict__ hb, int lane) {
    float b0r[4], b1r[4];
#pragma unroll
    for (int j = 0; j < 4; j++) {
        b0r[j] = __ldcg(hb + j * 512);
        b1r[j] = __ldcg(hb + j * 512 + 256);
    }
#pragma unroll 4
    for (int i = 0; i < 32; i++) {
        float b0f = b0r[i & 3], b1f = b1r[i & 3];
        if (i + 4 < 32) {
            b0r[i & 3] = __ldcg(hb + (i + 4) * 512);
            b1r[i & 3] = __ldcg(hb + (i + 4) * 512 + 256);
        }
        float4 vah = ah[i * 32 + lane];
        float4 val = al[i * 32 + lane];
        u32 bh0 = totf32(b0f), bh1 = totf32(b1f);
        u32 bl0 = totf32(b0f - __uint_as_float(bh0));
        u32 bl1 = totf32(b1f - __uint_as_float(bh1));
        u32 a0 = __float_as_uint(vah.x), a1 = __float_as_uint(vah.y);
        u32 a2 = __float_as_uint(vah.z), a3 = __float_as_uint(vah.w);
        mma8(d, a0, a1, a2, a3, bh0, bh1);
        mma8(d, a0, a1, a2, a3, bl0, bl1);
        mma8(d, __float_as_uint(val.x), __float_as_uint(val.y),
                __float_as_uint(val.z), __float_as_uint(val.w), bh0, bh1);
    }
}

__global__ void __launch_bounds__(NTHR, 1) lstm_rec(const float* __restrict__ Whh0,
                                                    const float* __restrict__ Wih1,
                                                    const float* __restrict__ Whh1,
                                                    const float* __restrict__ b1) {
    extern __shared__ float sm[];
    float* pbuf = sm + PBUF;

    const int tid = threadIdx.x;
    const int u0  = blockIdx.x * 4;

    stage_w(Whh0, sm + AW0H,  sm + AW0L,  u0);
    stage_w(Wih1, sm + AW1IH, sm + AW1IL, u0);
    stage_w(Whh1, sm + AW1HH, sm + AW1HL, u0);
    __syncthreads();

    // mma role
    const int w    = tid >> 5;        // 0..15
    const int nt   = w & 7;           // n-tile (8 batch)
    const int kh   = w >> 3;          // k-half
    const int lane = tid & 31;
    const int gid  = lane >> 2;
    const int tig  = lane & 3;
    const int ncol = nt * 8 + gid;
    const int hkof = (kh * 256 + tig) * 64 + ncol;   // B base offset into h
    const int apof = kh * 32 * 32;                   // float4 offset for k-half
    // update role (tid < 256)
    const int uu = tid >> 6;
    const int bb = tid & 63;
    float c0 = 0.f, c1 = 0.f;
    float b1v[4] = {0.f, 0.f, 0.f, 0.f};
    if (tid < 256)
#pragma unroll
        for (int g = 0; g < 4; g++) b1v[g] = b1[(g << 9) + u0 + uu];

    const float4* a0h = (const float4*)(sm + AW0H)  + apof;
    const float4* a0l = (const float4*)(sm + AW0L)  + apof;
    const float4* aih = (const float4*)(sm + AW1IH) + apof;
    const float4* ail = (const float4*)(sm + AW1IL) + apof;
    const float4* ahh = (const float4*)(sm + AW1HH) + apof;
    const float4* ahl = (const float4*)(sm + AW1HL) + apof;

    for (int t = 0; t < Tlen; t++) {
        const int p = t & 1;

        float xgv[4] = {0.f, 0.f, 0.f, 0.f};
        if (tid < 256)
#pragma unroll
            for (int g = 0; g < 4; g++)
                xgv[g] = __ldcs(&g_xg[((size_t)t * G4H + (g << 9) + u0 + uu) * Bsz + bb]);

        // ========== phase 1: gates0 partials over k-half ==========
        {
            float d[4] = {0.f, 0.f, 0.f, 0.f};
            mma_slice(d, a0h, a0l, g_h0 + (p ^ 1) * HB + hkof, lane);
            *(float2*)&pbuf[(kh * 16 + gid) * 66 + nt * 8 + 2 * tig]       = make_float2(d[0], d[1]);
            *(float2*)&pbuf[(kh * 16 + gid + 8) * 66 + nt * 8 + 2 * tig]   = make_float2(d[2], d[3]);
        }
        __syncthreads();
        if (tid < 256) {
            float s[4];
#pragma unroll
            for (int g = 0; g < 4; g++) {
                int r = uu * 4 + g;
                s[g] = xgv[g] + pbuf[r * 66 + bb] + pbuf[(16 + r) * 66 + bb];
            }
            c0 = sigm(s[1]) * c0 + sigm(s[0]) * tanh_fast(s[2]);
            float h0n = sigm(s[3]) * tanh_fast(c0);
            g_h0[p * HB + (u0 + uu) * 64 + bb] = h0n;
        }
        __syncthreads();
        bar_arrive(&g_bar1);

        // ========== phase 2: Whh1 part (h1_prev), then Wih1 part (h0n) ==========
        {
            float d[4] = {0.f, 0.f, 0.f, 0.f};
            bar_wait(&g_bar2, NCTA * (unsigned)t);
            mma_slice(d, ahh, ahl, g_h1 + (p ^ 1) * HB + hkof, lane);
            bar_wait(&g_bar1, NCTA * (unsigned)(t + 1));
            mma_slice(d, aih, ail, g_h0 + p * HB + hkof, lane);
            *(float2*)&pbuf[(kh * 16 + gid) * 66 + nt * 8 + 2 * tig]       = make_float2(d[0], d[1]);
            *(float2*)&pbuf[(kh * 16 + gid + 8) * 66 + nt * 8 + 2 * tig]   = make_float2(d[2], d[3]);
        }
        __syncthreads();
        if (tid < 256) {
            float s[4];
#pragma unroll
            for (int g = 0; g < 4; g++) {
                int r = uu * 4 + g;
                s[g] = b1v[g] + pbuf[r * 66 + bb] + pbuf[(16 + r) * 66 + bb];
            }
            c1 = sigm(s[1]) * c1 + sigm(s[0]) * tanh_fast(s[2]);
            float h1n = sigm(s[3]) * tanh_fast(c1);
            g_h1[p * HB + (u0 + uu) * 64 + bb] = h1n;
        }
        __syncthreads();
        bar_arrive(&g_bar2);
    }
}

// =================================================================
__global__ void __launch_bounds__(1024) kclf(const float* __restrict__ Wclf,
                                             const float* __restrict__ bclf,
                                             float* __restrict__ out) {
    __shared__ float red[1024];
    const int t  = threadIdx.x;
    const int o  = t & 1;
    const int b  = (t >> 1) & 63;
    const int ks = t >> 7;
    const float* h = g_h1 + HB;       // parity of t=511 is 1
    float s = 0.f;
#pragma unroll 8
    for (int i = 0; i < 64; i++) {
        int k = ks * 64 + i;
        s = fmaf(Wclf[o * Hd + k], h[k * 64 + b], s);
    }
    red[t] = s;
    __syncthreads();
    if (ks == 0) {
        float v = s + bclf[o];
#pragma unroll
        for (int w8 = 1; w8 < 8; w8++) v += red[t + w8 * 128];
        out[b * 2 + o] = v;
    }
}

// =================================================================
extern "C" void kernel_launch(void* const* d_in, const int* in_sizes, int n_in,
                              void* d_out, int out_size) {
    const int*   x    = (const int*)  d_in[0];
    const float* emb  = (const float*)d_in[1];
    const float* Wih0 = (const float*)d_in[2];
    const float* Whh0 = (const float*)d_in[3];
    const float* b0   = (const float*)d_in[4];
    const float* Wih1 = (const float*)d_in[5];
    const float* Whh1 = (const float*)d_in[6];
    const float* b1   = (const float*)d_in[7];
    const float* Wclf = (const float*)d_in[8];
    const float* bclf = (const float*)d_in[9];
    float* out = (float*)d_out;

    cudaFuncSetAttribute(lstm_rec, cudaFuncAttributeMaxDynamicSharedMemorySize, SMEMB);

    kzero<<<256, 256>>>();
    dim3 gA(Tlen, 32);
    kA<<<gA, 256>>>(x, emb, Wih0, b0);
    lstm_rec<<<NCTA, NTHR, SMEMB>>>(Whh0, Wih1, Whh1, b1);
    kclf<<<1, 1024>>>(Wclf, bclf, out);
}

// round 11
// speedup vs baseline: 1.2458x; 1.2458x over previous
#include <cuda_runtime.h>
#include <cstdint>
#include <cstddef>

#define Bsz  64
#define Hd   512
#define Tlen 512
#define G4H  2048
#define Ed   256
#define NCTA 128
#define NTHR 512
#define HB   (Hd * Bsz)
#define PPAD 18

typedef unsigned long long ull;

// ---------------- device scratch (static, allowed) ----------------
__device__ __align__(256) float g_xg[(size_t)Tlen * G4H * Bsz];  // 256 MB
__device__ __align__(256) float g_h0[HB];        // single buffer (sole consumer per step)
__device__ __align__(256) float g_h1[2 * HB];    // ping-pong
__device__ unsigned g_bar1;
__device__ unsigned g_bar2;

// ---------------- packed f32x2 helpers ----------------
__device__ __forceinline__ ull pk2f(float x) {
    ull r; asm("mov.b64 %0, {%1, %1};" : "=l"(r) : "f"(x)); return r;
}
__device__ __forceinline__ void ffma2(ull& a, ull h, ull w) {
    asm("fma.rn.f32x2 %0, %1, %2, %0;" : "+l"(a) : "l"(h), "l"(w));
}
__device__ __forceinline__ void up2(ull v, float& x, float& y) {
    unsigned lo, hi;
    asm("mov.b64 {%0, %1}, %2;" : "=r"(lo), "=r"(hi) : "l"(v));
    x = __uint_as_float(lo); y = __uint_as_float(hi);
}
__device__ __forceinline__ float sigm(float x) {
    return __fdividef(1.f, 1.f + __expf(-x));
}
__device__ __forceinline__ float tanh_fast(float x) {
    float e = __expf(2.f * x);
    return 1.f - __fdividef(2.f, e + 1.f);
}

// ---------------- split grid barrier (monotonic) ----------------
__device__ __forceinline__ void bar_arrive(unsigned* ctr) {
    if (threadIdx.x == 0)
        asm volatile("red.release.gpu.global.add.u32 [%0], 1;" :: "l"(ctr) : "memory");
}
__device__ __forceinline__ void bar_wait(unsigned* ctr, unsigned target) {
    if (threadIdx.x == 0) {
        unsigned v;
        do {
            asm volatile("ld.acquire.gpu.global.u32 %0, [%1];" : "=r"(v) : "l"(ctr) : "memory");
        } while (v < target);
    }
    __syncthreads();
}

// =================================================================
// Kernel A (fp32 f32x2, unchanged from R8)
// =================================================================
__global__ void __launch_bounds__(256) kA(const int* __restrict__ x,
                                          const float* __restrict__ emb,
                                          const float* __restrict__ Wih0,
                                          const float* __restrict__ b0) {
    __shared__ float ws[64 * 33];
    __shared__ float xs2[32 * 66];
    __shared__ int   xr[64];
    const int tid = threadIdx.x;
    const int t   = blockIdx.x;
    const int rb  = blockIdx.y * 64;
    if (tid < 64) xr[tid] = x[tid * Tlen + t];
    __syncthreads();

    ull accA[4], accB[4];
#pragma unroll
    for (int j = 0; j < 4; j++) { accA[j] = 0ull; accB[j] = 0ull; }
    const int r4 = tid >> 4;
    const int q4 = (tid & 15) * 4;

    for (int ec = 0; ec < Ed; ec += 32) {
#pragma unroll
        for (int i = 0; i < 8; i++) {
            int idx = tid + i * 256;
            int a = idx >> 5, e = idx & 31;
            ws[a * 33 + e] = Wih0[(rb + a) * Ed + ec + e];
            xs2[e * 66 + a] = emb[(size_t)xr[a] * Ed + ec + e];
        }
        __syncthreads();
#pragma unroll 8
        for (int e = 0; e < 32; e++) {
            ull x01 = *(const ull*)&xs2[e * 66 + q4];
            ull x23 = *(const ull*)&xs2[e * 66 + q4 + 2];
#pragma unroll
            for (int j = 0; j < 4; j++) {
                ull w2 = pk2f(ws[(r4 * 4 + j) * 33 + e]);
                ffma2(accA[j], x01, w2);
                ffma2(accB[j], x23, w2);
            }
        }
        __syncthreads();
    }
#pragma unroll
    for (int j = 0; j < 4; j++) {
        int row = rb + r4 * 4 + j;
        float bv = b0[row];
        float4 o;
        up2(accA[j], o.x, o.y);
        up2(accB[j], o.z, o.w);
        o.x += bv; o.y += bv; o.z += bv; o.w += bv;
        *(float4*)(g_xg + ((size_t)t * G4H + row) * Bsz + q4) = o;
    }
}

// =================================================================
__global__ void kzero() {
    int i = blockIdx.x * 256 + threadIdx.x;   // grid 256 -> 65536
    if (i < HB) g_h0[i] = 0.f;
    g_h1[i & (2 * HB - 1)] = 0.f;
    if (i == 0) { g_bar1 = 0u; g_bar2 = 0u; }
}

// =================================================================
// Persistent recurrent kernel: fused-h0-pass schedule.
// 128 CTAs x 512 threads (16 warps; warp w owns k-slice w*32).
// smem: wT0[512][16] | wT1[1024][16] | pbuf[16][64][PPAD] | g0s[16*66]
// =================================================================
#define SM_WT0  0
#define SM_WT1  8192
#define SM_PBUF 24576
#define SM_G0S  (24576 + 16 * 64 * PPAD)
#define SM_TOTF (SM_G0S + 16 * 66)
#define SMEMB   (SM_TOTF * 4)

// single-weight 32-k slice (used for [A]: Whh1 @ h1_prev)
__device__ __forceinline__ void gemm1(ull (&acc)[4][4], const float* wT, int k0,
                                      const float* __restrict__ hsrc,
                                      int rh, int q) {
    const float4* hp = (const float4*)hsrc + q;
    float4 hbuf[8];
#pragma unroll
    for (int j = 0; j < 8; j++) hbuf[j] = __ldcg(hp + (size_t)(k0 + j) * 16);
#pragma unroll 8
    for (int i = 0; i < 32; i++) {
        float4 hc = hbuf[i & 7];
        if (i + 8 < 32) hbuf[i & 7] = __ldcg(hp + (size_t)(k0 + i + 8) * 16);
        const ulonglong2* wp = (const ulonglong2*)(wT + (k0 + i) * 16 + rh * 8);
        ulonglong2 wa = wp[0];
        ulonglong2 wb = wp[1];
        ull h2;
        h2 = pk2f(hc.x);
        ffma2(acc[0][0], wa.x, h2); ffma2(acc[1][0], wa.y, h2);
        ffma2(acc[2][0], wb.x, h2); ffma2(acc[3][0], wb.y, h2);
        h2 = pk2f(hc.y);
        ffma2(acc[0][1], wa.x, h2); ffma2(acc[1][1], wa.y, h2);
        ffma2(acc[2][1], wb.x, h2); ffma2(acc[3][1], wb.y, h2);
        h2 = pk2f(hc.z);
        ffma2(acc[0][2], wa.x, h2); ffma2(acc[1][2], wa.y, h2);
        ffma2(acc[2][2], wb.x, h2); ffma2(acc[3][2], wb.y, h2);
        h2 = pk2f(hc.w);
        ffma2(acc[0][3], wa.x, h2); ffma2(acc[1][3], wa.y, h2);
        ffma2(acc[2][3], wb.x, h2); ffma2(acc[3][3], wb.y, h2);
    }
}

// dual-weight 32-k slice over h0n: acc2 += Wih1@h, accP += Whh0@h
__device__ __forceinline__ void gemm_dual(ull (&a2)[4][4], ull (&aP)[4][4],
                                          const float* wI, const float* wH, int k0,
                                          const float* __restrict__ hsrc,
                                          int rh, int q) {
    const float4* hp = (const float4*)hsrc + q;
    float4 hbuf[8];
#pragma unroll
    for (int j = 0; j < 8; j++) hbuf[j] = __ldcg(hp + (size_t)(k0 + j) * 16);
#pragma unroll 8
    for (int i = 0; i < 32; i++) {
        float4 hc = hbuf[i & 7];
        if (i + 8 < 32) hbuf[i & 7] = __ldcg(hp + (size_t)(k0 + i + 8) * 16);
        const ulonglong2* wpI = (const ulonglong2*)(wI + (k0 + i) * 16 + rh * 8);
        const ulonglong2* wpH = (const ulonglong2*)(wH + (k0 + i) * 16 + rh * 8);
        ulonglong2 ia = wpI[0], ib = wpI[1];
        ulonglong2 ha = wpH[0], hb2 = wpH[1];
        ull h2;
        h2 = pk2f(hc.x);
        ffma2(a2[0][0], ia.x, h2); ffma2(a2[1][0], ia.y, h2);
        ffma2(a2[2][0], ib.x, h2); ffma2(a2[3][0], ib.y, h2);
        ffma2(aP[0][0], ha.x, h2); ffma2(aP[1][0], ha.y, h2);
        ffma2(aP[2][0], hb2.x, h2); ffma2(aP[3][0], hb2.y, h2);
        h2 = pk2f(hc.y);
        ffma2(a2[0][1], ia.x, h2); ffma2(a2[1][1], ia.y, h2);
        ffma2(a2[2][1], ib.x, h2); ffma2(a2[3][1], ib.y, h2);
        ffma2(aP[0][1], ha.x, h2); ffma2(aP[1][1], ha.y, h2);
        ffma2(aP[2][1], hb2.x, h2); ffma2(aP[3][1], hb2.y, h2);
        h2 = pk2f(hc.z);
        ffma2(a2[0][2], ia.x, h2); ffma2(a2[1][2], ia.y, h2);
        ffma2(a2[2][2], ib.x, h2); ffma2(a2[3][2], ib.y, h2);
        ffma2(aP[0][2], ha.x, h2); ffma2(aP[1][2], ha.y, h2);
        ffma2(aP[2][2], hb2.x, h2); ffma2(aP[3][2], hb2.y, h2);
        h2 = pk2f(hc.w);
        ffma2(a2[0][3], ia.x, h2); ffma2(a2[1][3], ia.y, h2);
        ffma2(a2[2][3], ib.x, h2); ffma2(a2[3][3], ib.y, h2);
        ffma2(aP[0][3], ha.x, h2); ffma2(aP[1][3], ha.y, h2);
        ffma2(aP[2][3], hb2.x, h2); ffma2(aP[3][3], hb2.y, h2);
    }
}

__device__ __forceinline__ void storep(float* pbuf, ull (&acc)[4][4],
                                       int w, int rh, int q) {
#pragma unroll
    for (int p = 0; p < 4; p++)
#pragma unroll
        for (int j = 0; j < 4; j++)
            *(ull*)&pbuf[(w * 64 + q * 4 + j) * PPAD + rh * 8 + 2 * p] = acc[p][j];
}

__global__ void __launch_bounds__(NTHR, 1) lstm_rec(const float* __restrict__ Whh0,
                                                    const float* __restrict__ Wih1,
                                                    const float* __restrict__ Whh1,
                                                    const float* __restrict__ b1) {
    extern __shared__ float sm[];
    float* wT0  = sm + SM_WT0;
    float* wT1  = sm + SM_WT1;
    float* pbuf = sm + SM_PBUF;
    float* g0s  = sm + SM_G0S;

    const int tid = threadIdx.x;
    const int u0  = blockIdx.x * 4;

    // stage weights once, transposed: wT[k][j], j = unit*4 + gate
    for (int idx = tid; idx < 512 * 16; idx += NTHR) {
        int j = idx >> 9, k = idx & 511;
        int row = ((j & 3) << 9) + u0 + (j >> 2);
        wT0[k * 16 + j] = Whh0[row * Hd + k];
    }
    for (int idx = tid; idx < 1024 * 16; idx += NTHR) {
        int j = idx >> 10, k = idx & 1023;
        int row = ((j & 3) << 9) + u0 + (j >> 2);
        wT1[k * 16 + j] = (k < 512) ? Wih1[row * Hd + k] : Whh1[row * Hd + (k - 512)];
    }
    // init r0sum region to 0 (h0(-1)=0 => Whh0 partials are 0)
    for (int idx = tid; idx < 16 * 66; idx += NTHR) g0s[idx] = 0.f;
    __syncthreads();

    const int w    = tid >> 5;
    const int lane = tid & 31;
    const int rh   = lane >> 4;
    const int q    = lane & 15;
    const int uu = tid >> 6;
    const int bb = tid & 63;
    float c0 = 0.f, c1 = 0.f;
    float b1v[4] = {0.f, 0.f, 0.f, 0.f};
    float xgv[4] = {0.f, 0.f, 0.f, 0.f};
    if (tid < 256) {
#pragma unroll
        for (int g = 0; g < 4; g++) b1v[g] = b1[(g << 9) + u0 + uu];
        // prologue: xg(0)
#pragma unroll
        for (int g = 0; g < 4; g++)
            xgv[g] = __ldcs(&g_xg[((size_t)0 * G4H + (g << 9) + u0 + uu) * Bsz + bb]);
    }

    for (int t = 0; t < Tlen; t++) {
        const int p = t & 1;

        // ===== [B] h0(t) update from r0sum (g0s) + xg(t) =====
        if (tid < 256) {
            float s[4];
#pragma unroll
            for (int g = 0; g < 4; g++)
                s[g] = g0s[(uu * 4 + g) * 66 + bb] + xgv[g];
            c0 = sigm(s[1]) * c0 + sigm(s[0]) * tanh_fast(s[2]);
            float h0n = sigm(s[3]) * tanh_fast(c0);
            g_h0[(u0 + uu) * 64 + bb] = h0n;
        }
        __syncthreads();           // h0 stores + g0s reads complete
        bar_arrive(&g_bar1);       // publish h0(t)

        // ===== [A] acc2 = Whh1 @ h1(t-1)  (bar2 wait is long-satisfied) =====
        ull acc2[4][4], accP[4][4];
#pragma unroll
        for (int a = 0; a < 4; a++)
#pragma unroll
            for (int b = 0; b < 4; b++) { acc2[a][b] = 0ull; accP[a][b] = 0ull; }
        bar_wait(&g_bar2, NCTA * (unsigned)t);
        gemm1(acc2, wT1 + 512 * 16, w * 32, g_h1 + (p ^ 1) * HB, rh, q);

        // ===== [C] wait bar1, then dual pass over h0(t) =====
        bar_wait(&g_bar1, NCTA * (unsigned)(t + 1));
        if (tid < 256) {           // prefetch xg(t+1), hidden under [C] FFMA
            int tn = (t + 1 < Tlen) ? t + 1 : t;
#pragma unroll
            for (int g = 0; g < 4; g++)
                xgv[g] = __ldcs(&g_xg[((size_t)tn * G4H + (g << 9) + u0 + uu) * Bsz + bb]);
        }
        gemm_dual(acc2, accP, wT1, wT0, w * 32, g_h0, rh, q);

        // ===== [D] reduce gates1 -> h1(t); publish; reduce accP -> r0sum =====
        storep(pbuf, acc2, w, rh, q);
        __syncthreads();
        if (tid < 256) {
            float s[4] = {b1v[0], b1v[1], b1v[2], b1v[3]};
#pragma unroll
            for (int w16 = 0; w16 < 16; w16++) {
                const float* pp = &pbuf[(w16 * 64 + bb) * PPAD + uu * 4];
                float2 v0 = *(const float2*)pp;
                float2 v1 = *(const float2*)(pp + 2);
                s[0] += v0.x; s[1] += v0.y; s[2] += v1.x; s[3] += v1.y;
            }
            c1 = sigm(s[1]) * c1 + sigm(s[0]) * tanh_fast(s[2]);
            float h1n = sigm(s[3]) * tanh_fast(c1);
            g_h1[p * HB + (u0 + uu) * 64 + bb] = h1n;
        }
        __syncthreads();           // h1 stores + pbuf reads done
        bar_arrive(&g_bar2);       // publish h1(t) early

        storep(pbuf, accP, w, rh, q);
        __syncthreads();
        if (tid < 256) {
            float s[4] = {0.f, 0.f, 0.f, 0.f};
#pragma unroll
            for (int w16 = 0; w16 < 16; w16++) {
                const float* pp = &pbuf[(w16 * 64 + bb) * PPAD + uu * 4];
                float2 v0 = *(const float2*)pp;
                float2 v1 = *(const float2*)(pp + 2);
                s[0] += v0.x; s[1] += v0.y; s[2] += v1.x; s[3] += v1.y;
            }
#pragma unroll
            for (int g = 0; g < 4; g++)
                g0s[(uu * 4 + g) * 66 + bb] = s[g];
        }
        // pbuf/g0s hazards vs next step covered by [B]'s __syncthreads and
        // [A]'s bar_wait-internal __syncthreads.
        __syncthreads();
    }
}

// =================================================================
__global__ void __launch_bounds__(1024) kclf(const float* __restrict__ Wclf,
                                             const float* __restrict__ bclf,
                                             float* __restrict__ out) {
    __shared__ float red[1024];
    const int t  = threadIdx.x;
    const int o  = t & 1;
    const int b  = (t >> 1) & 63;
    const int ks = t >> 7;
    const float* h = g_h1 + HB;       // t=511 parity 1
    float s = 0.f;
#pragma unroll 8
    for (int i = 0; i < 64; i++) {
        int k = ks * 64 + i;
        s = fmaf(Wclf[o * Hd + k], h[k * 64 + b], s);
    }
    red[t] = s;
    __syncthreads();
    if (ks == 0) {
        float v = s + bclf[o];
#pragma unroll
        for (int w8 = 1; w8 < 8; w8++) v += red[t + w8 * 128];
        out[b * 2 + o] = v;
    }
}

// =================================================================
extern "C" void kernel_launch(void* const* d_in, const int* in_sizes, int n_in,
                              void* d_out, int out_size) {
    const int*   x    = (const int*)  d_in[0];
    const float* emb  = (const float*)d_in[1];
    const float* Wih0 = (const float*)d_in[2];
    const float* Whh0 = (const float*)d_in[3];
    const float* b0   = (const float*)d_in[4];
    const float* Wih1 = (const float*)d_in[5];
    const float* Whh1 = (const float*)d_in[6];
    const float* b1   = (const float*)d_in[7];
    const float* Wclf = (const float*)d_in[8];
    const float* bclf = (const float*)d_in[9];
    float* out = (float*)d_out;

    cudaFuncSetAttribute(lstm_rec, cudaFuncAttributeMaxDynamicSharedMemorySize, SMEMB);

    kzero<<<256, 256>>>();
    dim3 gA(Tlen, 32);
    kA<<<gA, 256>>>(x, emb, Wih0, b0);
    lstm_rec<<<NCTA, NTHR, SMEMB>>>(Whh0, Wih1, Whh1, b1);
    kclf<<<1, 1024>>>(Wclf, bclf, out);
}